// round 2
// baseline (speedup 1.0000x reference)
#include <cuda_runtime.h>

#define TPB 128
#define NSTEP 7

// ---------- fast exact-enough transcendentals ----------
__device__ __forceinline__ float fex2(float x) {
    float y; asm("ex2.approx.f32 %0, %1;" : "=f"(y) : "f"(x)); return y;
}
__device__ __forceinline__ float frcp(float x) {
    float y; asm("rcp.approx.f32 %0, %1;" : "=f"(y) : "f"(x)); return y;
}
// u is already -log2(e) * (pre-activation). sigmoid = 1/(1+exp(-a)) = rcp(1+ex2(u))
__device__ __forceinline__ float sig_p(float u) {
    return frcp(1.0f + fex2(u));
}

struct GruW {
    float wih[6][2];
    float whh[6][2];
    float bih[6];
    float bhh[6];
};

// Load GRU weights and pre-scale:
//   rows 0..3 (r,z gates)  * -log2(e)
//   rows 4..5 (n gate)     * -2*log2(e)   (tanh(a) = 2*sigmoid(2a)-1)
__device__ __forceinline__ void load_gru(GruW& W,
                                         const float* __restrict__ wih,
                                         const float* __restrict__ whh,
                                         const float* __restrict__ bih,
                                         const float* __restrict__ bhh) {
    const float L2E = 1.4426950408889634f;
#pragma unroll
    for (int k = 0; k < 6; ++k) {
        const float sc = (k < 4) ? -L2E : (-2.0f * L2E);
        W.wih[k][0] = __ldg(wih + 2 * k + 0) * sc;
        W.wih[k][1] = __ldg(wih + 2 * k + 1) * sc;
        W.whh[k][0] = __ldg(whh + 2 * k + 0) * sc;
        W.whh[k][1] = __ldg(whh + 2 * k + 1) * sc;
        W.bih[k]    = __ldg(bih + k) * sc;
        W.bhh[k]    = __ldg(bhh + k) * sc;
    }
}

// One GRUCell step, hidden size 2, input (a,b). h0,h1 updated in place.
// All weights pre-scaled as above, so gates are rcp(1+ex2(.)).
__device__ __forceinline__ void gru_cell(float a, float b,
                                         float& h0, float& h1,
                                         const GruW& W) {
    // gi_k = scaled( wih[k]·x + bih[k] )
    float gi0 = fmaf(W.wih[0][0], a, fmaf(W.wih[0][1], b, W.bih[0]));
    float gi1 = fmaf(W.wih[1][0], a, fmaf(W.wih[1][1], b, W.bih[1]));
    float gi2 = fmaf(W.wih[2][0], a, fmaf(W.wih[2][1], b, W.bih[2]));
    float gi3 = fmaf(W.wih[3][0], a, fmaf(W.wih[3][1], b, W.bih[3]));
    float gi4 = fmaf(W.wih[4][0], a, fmaf(W.wih[4][1], b, W.bih[4]));
    float gi5 = fmaf(W.wih[5][0], a, fmaf(W.wih[5][1], b, W.bih[5]));
    // gh_k = scaled( whh[k]·h + bhh[k] )
    float gh0 = fmaf(W.whh[0][0], h0, fmaf(W.whh[0][1], h1, W.bhh[0]));
    float gh1 = fmaf(W.whh[1][0], h0, fmaf(W.whh[1][1], h1, W.bhh[1]));
    float gh2 = fmaf(W.whh[2][0], h0, fmaf(W.whh[2][1], h1, W.bhh[2]));
    float gh3 = fmaf(W.whh[3][0], h0, fmaf(W.whh[3][1], h1, W.bhh[3]));
    float gh4 = fmaf(W.whh[4][0], h0, fmaf(W.whh[4][1], h1, W.bhh[4]));
    float gh5 = fmaf(W.whh[5][0], h0, fmaf(W.whh[5][1], h1, W.bhh[5]));

    float r0 = sig_p(gi0 + gh0);
    float r1 = sig_p(gi1 + gh1);
    float z0 = sig_p(gi2 + gh2);
    float z1 = sig_p(gi3 + gh3);

    // n = tanh(i_n + r*h_n): arg already scaled by -2*log2(e) through weights
    float t0 = sig_p(fmaf(r0, gh4, gi4));
    float t1 = sig_p(fmaf(r1, gh5, gi5));
    float n0 = fmaf(2.0f, t0, -1.0f);
    float n1 = fmaf(2.0f, t1, -1.0f);

    // h = (1-z)*n + z*h = n + z*(h - n)
    h0 = fmaf(z0, h0 - n0, n0);
    h1 = fmaf(z1, h1 - n1, n1);
}

__global__ void __launch_bounds__(TPB)
rec_policy_kernel(const float* __restrict__ x,
                  const float* __restrict__ up_wih, const float* __restrict__ up_whh,
                  const float* __restrict__ up_bih, const float* __restrict__ up_bhh,
                  const float* __restrict__ dn_wih, const float* __restrict__ dn_whh,
                  const float* __restrict__ dn_bih, const float* __restrict__ dn_bhh,
                  const float* __restrict__ obs_w, const float* __restrict__ obs_b,
                  const float* __restrict__ out_w, const float* __restrict__ out_b,
                  float* __restrict__ out, int B) {
    __shared__ float s[TPB * 19];           // input stage; reused for output stage
    const int tid = threadIdx.x;
    const int b0  = blockIdx.x * TPB;
    const int nrows = min(TPB, B - b0);     // full blocks on the bench shape

    // ---- stage input [nrows x 19] coalesced ----
    if (nrows == TPB) {
        const float4* src = (const float4*)(x + (size_t)b0 * 19);
        float4* dst = (float4*)s;
        constexpr int N4 = TPB * 19 / 4;    // 608
#pragma unroll
        for (int i = 0; i < (N4 + TPB - 1) / TPB; ++i) {
            int idx = tid + i * TPB;
            if (idx < N4) dst[idx] = src[idx];
        }
    } else {
        for (int idx = tid; idx < nrows * 19; idx += TPB)
            s[idx] = x[(size_t)b0 * 19 + idx];
    }

    // ---- load + pre-scale weights (uniform, L1-broadcast) ----
    GruW up, dn;
    load_gru(up, up_wih, up_whh, up_bih, up_bhh);
    load_gru(dn, dn_wih, dn_whh, dn_bih, dn_bhh);
    float ow[2][7];
#pragma unroll
    for (int c = 0; c < 2; ++c)
#pragma unroll
        for (int i = 0; i < 7; ++i) ow[c][i] = __ldg(obs_w + c * 7 + i);
    const float ob0 = __ldg(obs_b + 0), ob1 = __ldg(obs_b + 1);
    const float w_o0 = __ldg(out_w + 0), w_o1 = __ldg(out_w + 1);
    const float b_o  = __ldg(out_b + 0);

    __syncthreads();

    const bool active = (tid < nrows);
    const float* row = s + tid * 19;        // 19 odd -> bank-conflict-free

    float hu0[NSTEP], hu1[NSTEP];
    float g0 = 0.0f, g1 = 0.0f;

    if (active) {
        // ---- up GRU over 7 steps ----
        float h0 = 0.0f, h1 = 0.0f;
#pragma unroll
        for (int t = 0; t < NSTEP; ++t) {
            float a = row[5 + t];
            float b = row[12 + t];
            gru_cell(a, b, h0, h1, up);
            hu0[t] = h0; hu1[t] = h1;
        }

        // ---- obs linear: h = [obs(5), h_last(2)] @ obs_w.T + obs_b ----
        float c0 = ob0, c1 = ob1;
#pragma unroll
        for (int i = 0; i < 5; ++i) {
            float o = row[i];
            c0 = fmaf(ow[0][i], o, c0);
            c1 = fmaf(ow[1][i], o, c1);
        }
        c0 = fmaf(ow[0][5], h0, c0); c0 = fmaf(ow[0][6], h1, c0);
        c1 = fmaf(ow[1][5], h0, c1); c1 = fmaf(ow[1][6], h1, c1);
        g0 = c0; g1 = c1;
    }

    __syncthreads();                        // done reading input stage

    // ---- down GRU + per-step output, write acts into smem ----
    float* orow = s + tid * 7;              // 7 odd -> bank-conflict-free
    if (active) {
#pragma unroll
        for (int t = 0; t < NSTEP; ++t) {
            gru_cell(hu0[t], hu1[t], g0, g1, dn);
            orow[t] = fmaf(w_o0, g0, fmaf(w_o1, g1, b_o));
        }
    }

    __syncthreads();

    // ---- stage output [nrows x 7] coalesced ----
    if (nrows == TPB) {
        float4* od = (float4*)(out + (size_t)b0 * 7);
        const float4* ss = (const float4*)s;
        constexpr int N4 = TPB * 7 / 4;     // 224
#pragma unroll
        for (int i = 0; i < (N4 + TPB - 1) / TPB; ++i) {
            int idx = tid + i * TPB;
            if (idx < N4) od[idx] = ss[idx];
        }
    } else {
        for (int idx = tid; idx < nrows * 7; idx += TPB)
            out[(size_t)b0 * 7 + idx] = s[idx];
    }
}

extern "C" void kernel_launch(void* const* d_in, const int* in_sizes, int n_in,
                              void* d_out, int out_size) {
    const float* x      = (const float*)d_in[0];
    const float* up_wih = (const float*)d_in[1];
    const float* up_whh = (const float*)d_in[2];
    const float* up_bih = (const float*)d_in[3];
    const float* up_bhh = (const float*)d_in[4];
    const float* dn_wih = (const float*)d_in[5];
    const float* dn_whh = (const float*)d_in[6];
    const float* dn_bih = (const float*)d_in[7];
    const float* dn_bhh = (const float*)d_in[8];
    const float* obs_w  = (const float*)d_in[9];
    const float* obs_b  = (const float*)d_in[10];
    const float* out_w  = (const float*)d_in[11];
    const float* out_b  = (const float*)d_in[12];
    float* out = (float*)d_out;

    const int B = in_sizes[0] / 19;
    const int grid = (B + TPB - 1) / TPB;
    rec_policy_kernel<<<grid, TPB>>>(x,
                                     up_wih, up_whh, up_bih, up_bhh,
                                     dn_wih, dn_whh, dn_bih, dn_bhh,
                                     obs_w, obs_b, out_w, out_b,
                                     out, B);
}

// round 4
// speedup vs baseline: 1.6158x; 1.6158x over previous
#include <cuda_runtime.h>

#define TPB 128
#define NSTEP 7

typedef unsigned long long u64;

// ---------- f32x2 packed helpers ----------
__device__ __forceinline__ u64 pk(float lo, float hi) {
    u64 d; asm("mov.b64 %0, {%1, %2};" : "=l"(d) : "f"(lo), "f"(hi)); return d;
}
__device__ __forceinline__ void unpk(u64 d, float& lo, float& hi) {
    asm("mov.b64 {%0, %1}, %2;" : "=f"(lo), "=f"(hi) : "l"(d));
}
__device__ __forceinline__ u64 fma2_(u64 a, u64 b, u64 c) {
    u64 d; asm("fma.rn.f32x2 %0, %1, %2, %3;" : "=l"(d) : "l"(a), "l"(b), "l"(c)); return d;
}
__device__ __forceinline__ u64 add2_(u64 a, u64 b) {
    u64 d; asm("add.rn.f32x2 %0, %1, %2;" : "=l"(d) : "l"(a), "l"(b)); return d;
}
// ---------- scalar fast math ----------
__device__ __forceinline__ float fex2(float x) {
    float y; asm("ex2.approx.f32 %0, %1;" : "=f"(y) : "f"(x)); return y;
}
__device__ __forceinline__ float frcp(float x) {
    float y; asm("rcp.approx.f32 %0, %1;" : "=f"(y) : "f"(x)); return y;
}
__device__ __forceinline__ float ftanh(float x) {
    float y; asm("tanh.approx.f32 %0, %1;" : "=f"(y) : "f"(x)); return y;
}

// One GRU cell, hidden=2, input (aa,bb) = broadcast-packed scalars.
// W layout (u64 pairs, lanes = hidden index 0/1):
//  [0..4]  r gate: wx0, wx1, wh0, wh1, bias   (all prescaled by 0.5; bih+bhh fused)
//  [5..9]  z gate: same
//  [10..12] n gi:  nx0, nx1, nbi              (prescaled by c = -2*log2(e))
//  [13..15] n gh:  nh0, nh1, nbh              (prescaled by c/2 = -log2(e))
// r = 0.5*(1+tanh(u_r));  arg = c*(i_n + r*h_n) = s + t_r*gh ;  n = 2*rcp(1+ex2(arg))-1
__device__ __forceinline__ void gru_cell(u64 aa, u64 bb, float& h0, float& h1,
                                         const u64* __restrict__ W) {
    u64 hh0 = pk(h0, h0), hh1 = pk(h1, h1);
    u64 ur = fma2_(W[0], aa, fma2_(W[1], bb, fma2_(W[2], hh0, fma2_(W[3], hh1, W[4]))));
    u64 uz = fma2_(W[5], aa, fma2_(W[6], bb, fma2_(W[7], hh0, fma2_(W[8], hh1, W[9]))));
    float ur0, ur1, uz0, uz1;
    unpk(ur, ur0, ur1); unpk(uz, uz0, uz1);
    float tr0 = ftanh(ur0), tr1 = ftanh(ur1);
    float tz0 = ftanh(uz0), tz1 = ftanh(uz1);

    u64 gi = fma2_(W[10], aa, fma2_(W[11], bb, W[12]));
    u64 gh = fma2_(W[13], hh0, fma2_(W[14], hh1, W[15]));
    u64 s  = add2_(gi, gh);
    u64 tr2 = pk(tr0, tr1);
    u64 arg = fma2_(tr2, gh, s);
    float a0, a1; unpk(arg, a0, a1);

    float n0 = fmaf(2.0f, frcp(1.0f + fex2(a0)), -1.0f);
    float n1 = fmaf(2.0f, frcp(1.0f + fex2(a1)), -1.0f);
    float z0 = fmaf(0.5f, tz0, 0.5f);
    float z1 = fmaf(0.5f, tz1, 0.5f);
    h0 = fmaf(z0, h0 - n0, n0);
    h1 = fmaf(z1, h1 - n1, n1);
}

// smem float offsets for prepped weights
#define W_UP   0
#define W_DN   32
#define W_OBS  64
#define W_OUT  80
#define W_FLTS 84   // 84*4=336B (16B multiple)

__global__ void __launch_bounds__(TPB)
rec_policy_kernel(const float* __restrict__ x,
                  const float* __restrict__ up_wih, const float* __restrict__ up_whh,
                  const float* __restrict__ up_bih, const float* __restrict__ up_bhh,
                  const float* __restrict__ dn_wih, const float* __restrict__ dn_whh,
                  const float* __restrict__ dn_bih, const float* __restrict__ dn_bhh,
                  const float* __restrict__ obs_w, const float* __restrict__ obs_b,
                  const float* __restrict__ out_w, const float* __restrict__ out_b,
                  float* __restrict__ out, int B) {
    __shared__ __align__(16) float sw[W_FLTS];
    __shared__ __align__(16) float s[TPB * 19];   // input stage; reused for output
    const int tid = threadIdx.x;
    const int b0  = blockIdx.x * TPB;
    const int nrows = min(TPB, B - b0);

    // ---- thread 0: compute packed+prescaled weights into smem ----
    if (tid == 0) {
        const float L2E = 1.4426950408889634f;
        const float c = -2.0f * L2E;
#pragma unroll
        for (int g = 0; g < 2; ++g) {
            const float* wih = g ? dn_wih : up_wih;
            const float* whh = g ? dn_whh : up_whh;
            const float* bih = g ? dn_bih : up_bih;
            const float* bhh = g ? dn_bhh : up_bhh;
            float* W = sw + (g ? W_DN : W_UP);
#pragma unroll
            for (int G = 0; G < 2; ++G) {    // r (rows 0,1), z (rows 2,3)
                float* p = W + G * 10;
                p[0] = 0.5f * wih[4*G + 0]; p[1] = 0.5f * wih[4*G + 2];
                p[2] = 0.5f * wih[4*G + 1]; p[3] = 0.5f * wih[4*G + 3];
                p[4] = 0.5f * whh[4*G + 0]; p[5] = 0.5f * whh[4*G + 2];
                p[6] = 0.5f * whh[4*G + 1]; p[7] = 0.5f * whh[4*G + 3];
                p[8] = 0.5f * (bih[2*G + 0] + bhh[2*G + 0]);
                p[9] = 0.5f * (bih[2*G + 1] + bhh[2*G + 1]);
            }
            // n gate (rows 4,5)
            W[20] = c * wih[8];  W[21] = c * wih[10];
            W[22] = c * wih[9];  W[23] = c * wih[11];
            W[24] = c * bih[4];  W[25] = c * bih[5];
            const float ch = 0.5f * c;
            W[26] = ch * whh[8]; W[27] = ch * whh[10];
            W[28] = ch * whh[9]; W[29] = ch * whh[11];
            W[30] = ch * bhh[4]; W[31] = ch * bhh[5];
        }
#pragma unroll
        for (int j = 0; j < 7; ++j) {
            sw[W_OBS + 2*j + 0] = obs_w[j];
            sw[W_OBS + 2*j + 1] = obs_w[7 + j];
        }
        sw[W_OBS + 14] = obs_b[0];
        sw[W_OBS + 15] = obs_b[1];
        sw[W_OUT + 0] = out_w[0];
        sw[W_OUT + 1] = out_w[1];
        sw[W_OUT + 2] = out_b[0];
        sw[W_OUT + 3] = 0.0f;
    }

    // ---- stage input [nrows x 19] coalesced ----
    if (nrows == TPB) {
        const float4* src = (const float4*)(x + (size_t)b0 * 19);
        float4* dst = (float4*)s;
        constexpr int N4 = TPB * 19 / 4;    // 608
#pragma unroll
        for (int i = 0; i < (N4 + TPB - 1) / TPB; ++i) {
            int idx = tid + i * TPB;
            if (idx < N4) dst[idx] = src[idx];
        }
    } else {
        for (int idx = tid; idx < nrows * 19; idx += TPB)
            s[idx] = x[(size_t)b0 * 19 + idx];
    }
    __syncthreads();

    const bool active = (tid < nrows);
    const float* row = s + tid * 19;        // 19 odd -> bank-conflict-free

    float hu0[NSTEP], hu1[NSTEP];
    float g0 = 0.0f, g1 = 0.0f;

    if (active) {
        // ---- load up-GRU packed weights (8x LDS.128 broadcast) ----
        u64 UW[16];
        {
            const ulonglong2* p = (const ulonglong2*)(sw + W_UP);
#pragma unroll
            for (int i = 0; i < 8; ++i) { ulonglong2 v = p[i]; UW[2*i] = v.x; UW[2*i+1] = v.y; }
        }
        float h0 = 0.0f, h1 = 0.0f;
#pragma unroll
        for (int t = 0; t < NSTEP; ++t) {
            float a = row[5 + t];
            float b = row[12 + t];
            gru_cell(pk(a, a), pk(b, b), h0, h1, UW);
            hu0[t] = h0; hu1[t] = h1;
        }

        // ---- obs linear (packed over output lanes) ----
        u64 OW[8];
        {
            const ulonglong2* p = (const ulonglong2*)(sw + W_OBS);
#pragma unroll
            for (int i = 0; i < 4; ++i) { ulonglong2 v = p[i]; OW[2*i] = v.x; OW[2*i+1] = v.y; }
        }
        u64 c2 = OW[7];
#pragma unroll
        for (int j = 0; j < 5; ++j) {
            float o = row[j];
            c2 = fma2_(OW[j], pk(o, o), c2);
        }
        c2 = fma2_(OW[5], pk(h0, h0), c2);
        c2 = fma2_(OW[6], pk(h1, h1), c2);
        unpk(c2, g0, g1);
    }

    __syncthreads();                        // done reading input stage

    // ---- down GRU + per-step output ----
    float* orow = s + tid * 7;              // 7 odd -> bank-conflict-free
    if (active) {
        u64 DW[16];
        {
            const ulonglong2* p = (const ulonglong2*)(sw + W_DN);
#pragma unroll
            for (int i = 0; i < 8; ++i) { ulonglong2 v = p[i]; DW[2*i] = v.x; DW[2*i+1] = v.y; }
        }
        const float4 wo = *(const float4*)(sw + W_OUT);
#pragma unroll
        for (int t = 0; t < NSTEP; ++t) {
            gru_cell(pk(hu0[t], hu0[t]), pk(hu1[t], hu1[t]), g0, g1, DW);
            orow[t] = fmaf(wo.x, g0, fmaf(wo.y, g1, wo.z));
        }
    }

    __syncthreads();

    // ---- stage output [nrows x 7] coalesced ----
    if (nrows == TPB) {
        float4* od = (float4*)(out + (size_t)b0 * 7);
        const float4* ss = (const float4*)s;
        constexpr int N4 = TPB * 7 / 4;     // 224
#pragma unroll
        for (int i = 0; i < (N4 + TPB - 1) / TPB; ++i) {
            int idx = tid + i * TPB;
            if (idx < N4) od[idx] = ss[idx];
        }
    } else {
        for (int idx = tid; idx < nrows * 7; idx += TPB)
            out[(size_t)b0 * 7 + idx] = s[idx];
    }
}

extern "C" void kernel_launch(void* const* d_in, const int* in_sizes, int n_in,
                              void* d_out, int out_size) {
    const float* x      = (const float*)d_in[0];
    const float* up_wih = (const float*)d_in[1];
    const float* up_whh = (const float*)d_in[2];
    const float* up_bih = (const float*)d_in[3];
    const float* up_bhh = (const float*)d_in[4];
    const float* dn_wih = (const float*)d_in[5];
    const float* dn_whh = (const float*)d_in[6];
    const float* dn_bih = (const float*)d_in[7];
    const float* dn_bhh = (const float*)d_in[8];
    const float* obs_w  = (const float*)d_in[9];
    const float* obs_b  = (const float*)d_in[10];
    const float* out_w  = (const float*)d_in[11];
    const float* out_b  = (const float*)d_in[12];
    float* out = (float*)d_out;

    const int B = in_sizes[0] / 19;
    const int grid = (B + TPB - 1) / TPB;
    rec_policy_kernel<<<grid, TPB>>>(x,
                                     up_wih, up_whh, up_bih, up_bhh,
                                     dn_wih, dn_whh, dn_bih, dn_bhh,
                                     obs_w, obs_b, out_w, out_b,
                                     out, B);
}

// round 5
// speedup vs baseline: 1.8979x; 1.1746x over previous
#include <cuda_runtime.h>

#define TPB 128
#define NSTEP 7

typedef unsigned long long u64;

// ---------- f32x2 packed helpers ----------
__device__ __forceinline__ u64 pk(float lo, float hi) {
    u64 d; asm("mov.b64 %0, {%1, %2};" : "=l"(d) : "f"(lo), "f"(hi)); return d;
}
__device__ __forceinline__ void unpk(u64 d, float& lo, float& hi) {
    asm("mov.b64 {%0, %1}, %2;" : "=f"(lo), "=f"(hi) : "l"(d));
}
__device__ __forceinline__ u64 fma2_(u64 a, u64 b, u64 c) {
    u64 d; asm("fma.rn.f32x2 %0, %1, %2, %3;" : "=l"(d) : "l"(a), "l"(b), "l"(c)); return d;
}
__device__ __forceinline__ u64 add2_(u64 a, u64 b) {
    u64 d; asm("add.rn.f32x2 %0, %1, %2;" : "=l"(d) : "l"(a), "l"(b)); return d;
}
__device__ __forceinline__ float ftanh(float x) {
    float y; asm("tanh.approx.f32 %0, %1;" : "=f"(y) : "f"(x)); return y;
}

// One GRU cell, hidden=2, input (aa,bb) = broadcast-packed scalars.
// W layout (u64 pairs, lanes = hidden index 0/1):
//  [0..4]   r gate: wx0, wx1, wh0, wh1, bias   (prescaled 0.5; bih+bhh fused)
//  [5..9]   z gate: same
//  [10..12] n gi:   nx0, nx1, nbi              (UNscaled)
//  [13..15] n gh:   nh0, nh1, nbh              (prescaled 0.5)
// r = 0.5*(1+tanh(u_r));  z = 0.5*(1+tanh(u_z))
// arg = gi + gh' + t_r*gh'  (== i_n + r*h_n);  n = tanh(arg)
__device__ __forceinline__ void gru_cell(u64 aa, u64 bb, float& h0, float& h1,
                                         const u64* __restrict__ W) {
    u64 hh0 = pk(h0, h0), hh1 = pk(h1, h1);
    u64 ur = fma2_(W[0], aa, fma2_(W[1], bb, fma2_(W[2], hh0, fma2_(W[3], hh1, W[4]))));
    u64 uz = fma2_(W[5], aa, fma2_(W[6], bb, fma2_(W[7], hh0, fma2_(W[8], hh1, W[9]))));
    float ur0, ur1, uz0, uz1;
    unpk(ur, ur0, ur1); unpk(uz, uz0, uz1);
    float tr0 = ftanh(ur0), tr1 = ftanh(ur1);
    float tz0 = ftanh(uz0), tz1 = ftanh(uz1);

    u64 gi = fma2_(W[10], aa, fma2_(W[11], bb, W[12]));
    u64 gh = fma2_(W[13], hh0, fma2_(W[14], hh1, W[15]));
    u64 s  = add2_(gi, gh);
    u64 arg = fma2_(pk(tr0, tr1), gh, s);
    float a0, a1; unpk(arg, a0, a1);

    float n0 = ftanh(a0);
    float n1 = ftanh(a1);
    float z0 = fmaf(0.5f, tz0, 0.5f);
    float z1 = fmaf(0.5f, tz1, 0.5f);
    h0 = fmaf(z0, h0 - n0, n0);
    h1 = fmaf(z1, h1 - n1, n1);
}

// smem float offsets for prepped weights
#define W_UP   0
#define W_DN   32
#define W_OBS  64
#define W_OUT  80
#define W_FLTS 84

__global__ void __launch_bounds__(TPB)
rec_policy_kernel(const float* __restrict__ x,
                  const float* __restrict__ up_wih, const float* __restrict__ up_whh,
                  const float* __restrict__ up_bih, const float* __restrict__ up_bhh,
                  const float* __restrict__ dn_wih, const float* __restrict__ dn_whh,
                  const float* __restrict__ dn_bih, const float* __restrict__ dn_bhh,
                  const float* __restrict__ obs_w, const float* __restrict__ obs_b,
                  const float* __restrict__ out_w, const float* __restrict__ out_b,
                  float* __restrict__ out, int B) {
    __shared__ __align__(16) float sw[W_FLTS];
    __shared__ __align__(16) float s[TPB * 19];   // input stage
    __shared__ __align__(16) float so[TPB * 7];   // output stage (separate: no mid-sync)
    const int tid = threadIdx.x;
    const int b0  = blockIdx.x * TPB;
    const int nrows = min(TPB, B - b0);

    // ---- thread 0: compute packed+prescaled weights into smem ----
    if (tid == 0) {
#pragma unroll
        for (int g = 0; g < 2; ++g) {
            const float* wih = g ? dn_wih : up_wih;
            const float* whh = g ? dn_whh : up_whh;
            const float* bih = g ? dn_bih : up_bih;
            const float* bhh = g ? dn_bhh : up_bhh;
            float* W = sw + (g ? W_DN : W_UP);
#pragma unroll
            for (int G = 0; G < 2; ++G) {    // r (rows 0,1), z (rows 2,3)
                float* p = W + G * 10;
                p[0] = 0.5f * wih[4*G + 0]; p[1] = 0.5f * wih[4*G + 2];
                p[2] = 0.5f * wih[4*G + 1]; p[3] = 0.5f * wih[4*G + 3];
                p[4] = 0.5f * whh[4*G + 0]; p[5] = 0.5f * whh[4*G + 2];
                p[6] = 0.5f * whh[4*G + 1]; p[7] = 0.5f * whh[4*G + 3];
                p[8] = 0.5f * (bih[2*G + 0] + bhh[2*G + 0]);
                p[9] = 0.5f * (bih[2*G + 1] + bhh[2*G + 1]);
            }
            // n gate (rows 4,5): gi unscaled, gh scaled by 0.5
            W[20] = wih[8];  W[21] = wih[10];
            W[22] = wih[9];  W[23] = wih[11];
            W[24] = bih[4];  W[25] = bih[5];
            W[26] = 0.5f * whh[8]; W[27] = 0.5f * whh[10];
            W[28] = 0.5f * whh[9]; W[29] = 0.5f * whh[11];
            W[30] = 0.5f * bhh[4]; W[31] = 0.5f * bhh[5];
        }
#pragma unroll
        for (int j = 0; j < 7; ++j) {
            sw[W_OBS + 2*j + 0] = obs_w[j];
            sw[W_OBS + 2*j + 1] = obs_w[7 + j];
        }
        sw[W_OBS + 14] = obs_b[0];
        sw[W_OBS + 15] = obs_b[1];
        sw[W_OUT + 0] = out_w[0];
        sw[W_OUT + 1] = out_w[1];
        sw[W_OUT + 2] = out_b[0];
        sw[W_OUT + 3] = 0.0f;
    }

    // ---- stage input [nrows x 19] coalesced ----
    if (nrows == TPB) {
        const float4* src = (const float4*)(x + (size_t)b0 * 19);
        float4* dst = (float4*)s;
        constexpr int N4 = TPB * 19 / 4;    // 608
#pragma unroll
        for (int i = 0; i < (N4 + TPB - 1) / TPB; ++i) {
            int idx = tid + i * TPB;
            if (idx < N4) dst[idx] = src[idx];
        }
    } else {
        for (int idx = tid; idx < nrows * 19; idx += TPB)
            s[idx] = x[(size_t)b0 * 19 + idx];
    }
    __syncthreads();

    const bool active = (tid < nrows);
    const float* row = s + tid * 19;        // 19 odd -> bank-conflict-free

    if (active) {
        float hu0[NSTEP], hu1[NSTEP];

        // ---- up GRU (weights: 8x LDS.128 broadcast) ----
        u64 UW[16];
        {
            const ulonglong2* p = (const ulonglong2*)(sw + W_UP);
#pragma unroll
            for (int i = 0; i < 8; ++i) { ulonglong2 v = p[i]; UW[2*i] = v.x; UW[2*i+1] = v.y; }
        }
        float h0 = 0.0f, h1 = 0.0f;
#pragma unroll
        for (int t = 0; t < NSTEP; ++t) {
            float a = row[5 + t];
            float b = row[12 + t];
            gru_cell(pk(a, a), pk(b, b), h0, h1, UW);
            hu0[t] = h0; hu1[t] = h1;
        }

        // ---- obs linear (packed over output lanes) ----
        float g0, g1;
        {
            u64 OW[8];
            const ulonglong2* p = (const ulonglong2*)(sw + W_OBS);
#pragma unroll
            for (int i = 0; i < 4; ++i) { ulonglong2 v = p[i]; OW[2*i] = v.x; OW[2*i+1] = v.y; }
            u64 c2 = OW[7];
#pragma unroll
            for (int j = 0; j < 5; ++j) {
                float o = row[j];
                c2 = fma2_(OW[j], pk(o, o), c2);
            }
            c2 = fma2_(OW[5], pk(h0, h0), c2);
            c2 = fma2_(OW[6], pk(h1, h1), c2);
            unpk(c2, g0, g1);
        }

        // ---- down GRU + per-step output ----
        u64 DW[16];
        {
            const ulonglong2* p = (const ulonglong2*)(sw + W_DN);
#pragma unroll
            for (int i = 0; i < 8; ++i) { ulonglong2 v = p[i]; DW[2*i] = v.x; DW[2*i+1] = v.y; }
        }
        const float4 wo = *(const float4*)(sw + W_OUT);
        float* orow = so + tid * 7;         // 7 odd -> bank-conflict-free
#pragma unroll
        for (int t = 0; t < NSTEP; ++t) {
            gru_cell(pk(hu0[t], hu0[t]), pk(hu1[t], hu1[t]), g0, g1, DW);
            orow[t] = fmaf(wo.x, g0, fmaf(wo.y, g1, wo.z));
        }
    }

    __syncthreads();

    // ---- stage output [nrows x 7] coalesced ----
    if (nrows == TPB) {
        float4* od = (float4*)(out + (size_t)b0 * 7);
        const float4* ss = (const float4*)so;
        constexpr int N4 = TPB * 7 / 4;     // 224
#pragma unroll
        for (int i = 0; i < (N4 + TPB - 1) / TPB; ++i) {
            int idx = tid + i * TPB;
            if (idx < N4) od[idx] = ss[idx];
        }
    } else {
        for (int idx = tid; idx < nrows * 7; idx += TPB)
            out[(size_t)b0 * 7 + idx] = so[idx];
    }
}

extern "C" void kernel_launch(void* const* d_in, const int* in_sizes, int n_in,
                              void* d_out, int out_size) {
    const float* x      = (const float*)d_in[0];
    const float* up_wih = (const float*)d_in[1];
    const float* up_whh = (const float*)d_in[2];
    const float* up_bih = (const float*)d_in[3];
    const float* up_bhh = (const float*)d_in[4];
    const float* dn_wih = (const float*)d_in[5];
    const float* dn_whh = (const float*)d_in[6];
    const float* dn_bih = (const float*)d_in[7];
    const float* dn_bhh = (const float*)d_in[8];
    const float* obs_w  = (const float*)d_in[9];
    const float* obs_b  = (const float*)d_in[10];
    const float* out_w  = (const float*)d_in[11];
    const float* out_b  = (const float*)d_in[12];
    float* out = (float*)d_out;

    const int B = in_sizes[0] / 19;
    const int grid = (B + TPB - 1) / TPB;
    rec_policy_kernel<<<grid, TPB>>>(x,
                                     up_wih, up_whh, up_bih, up_bhh,
                                     dn_wih, dn_whh, dn_bih, dn_bhh,
                                     obs_w, obs_b, out_w, out_b,
                                     out, B);
}

// round 6
// speedup vs baseline: 1.9255x; 1.0145x over previous
#include <cuda_runtime.h>

#define TPB 128
#define ROWS_PER_BLOCK (2 * TPB)
#define NSTEP 7

typedef unsigned long long u64;

// ---------- f32x2 packed helpers ----------
__device__ __forceinline__ u64 pk(float lo, float hi) {
    u64 d; asm("mov.b64 %0, {%1, %2};" : "=l"(d) : "f"(lo), "f"(hi)); return d;
}
__device__ __forceinline__ void unpk(u64 d, float& lo, float& hi) {
    asm("mov.b64 {%0, %1}, %2;" : "=f"(lo), "=f"(hi) : "l"(d));
}
__device__ __forceinline__ u64 fma2_(u64 a, u64 b, u64 c) {
    u64 d; asm("fma.rn.f32x2 %0, %1, %2, %3;" : "=l"(d) : "l"(a), "l"(b), "l"(c)); return d;
}
__device__ __forceinline__ u64 add2_(u64 a, u64 b) {
    u64 d; asm("add.rn.f32x2 %0, %1, %2;" : "=l"(d) : "l"(a), "l"(b)); return d;
}
__device__ __forceinline__ float ftanh(float x) {
    float y; asm("tanh.approx.f32 %0, %1;" : "=f"(y) : "f"(x)); return y;
}

// One GRU cell, hidden=2, input (aa,bb) = broadcast-packed scalars.
// W layout (u64 pairs, lanes = hidden index 0/1):
//  [0..4]   r gate: wx0, wx1, wh0, wh1, bias   (prescaled 0.5; bih+bhh fused)
//  [5..9]   z gate: same
//  [10..12] n gi:   nx0, nx1, nbi              (UNscaled)
//  [13..15] n gh:   nh0, nh1, nbh              (prescaled 0.5)
// r = 0.5*(1+tanh(u_r));  z = 0.5*(1+tanh(u_z))
// arg = gi + gh' + t_r*gh'  (== i_n + r*h_n);  n = tanh(arg)
__device__ __forceinline__ void gru_cell(u64 aa, u64 bb, float& h0, float& h1,
                                         const u64* __restrict__ W) {
    u64 hh0 = pk(h0, h0), hh1 = pk(h1, h1);
    u64 ur = fma2_(W[0], aa, fma2_(W[1], bb, fma2_(W[2], hh0, fma2_(W[3], hh1, W[4]))));
    u64 uz = fma2_(W[5], aa, fma2_(W[6], bb, fma2_(W[7], hh0, fma2_(W[8], hh1, W[9]))));
    float ur0, ur1, uz0, uz1;
    unpk(ur, ur0, ur1); unpk(uz, uz0, uz1);
    float tr0 = ftanh(ur0), tr1 = ftanh(ur1);
    float tz0 = ftanh(uz0), tz1 = ftanh(uz1);

    u64 gi = fma2_(W[10], aa, fma2_(W[11], bb, W[12]));
    u64 gh = fma2_(W[13], hh0, fma2_(W[14], hh1, W[15]));
    u64 s  = add2_(gi, gh);
    u64 arg = fma2_(pk(tr0, tr1), gh, s);
    float a0, a1; unpk(arg, a0, a1);

    float n0 = ftanh(a0);
    float n1 = ftanh(a1);
    float z0 = fmaf(0.5f, tz0, 0.5f);
    float z1 = fmaf(0.5f, tz1, 0.5f);
    h0 = fmaf(z0, h0 - n0, n0);
    h1 = fmaf(z1, h1 - n1, n1);
}

// smem float offsets for prepped weights
#define W_UP   0
#define W_DN   32
#define W_OBS  64
#define W_OUT  80
#define W_FLTS 84

__global__ void __launch_bounds__(TPB)
rec_policy_kernel(const float* __restrict__ x,
                  const float* __restrict__ up_wih, const float* __restrict__ up_whh,
                  const float* __restrict__ up_bih, const float* __restrict__ up_bhh,
                  const float* __restrict__ dn_wih, const float* __restrict__ dn_whh,
                  const float* __restrict__ dn_bih, const float* __restrict__ dn_bhh,
                  const float* __restrict__ obs_w, const float* __restrict__ obs_b,
                  const float* __restrict__ out_w, const float* __restrict__ out_b,
                  float* __restrict__ out, int B) {
    __shared__ __align__(16) float sw[W_FLTS];
    __shared__ __align__(16) float s[ROWS_PER_BLOCK * 19];   // input stage
    __shared__ __align__(16) float so[ROWS_PER_BLOCK * 7];   // output stage
    const int tid = threadIdx.x;
    const int b0  = blockIdx.x * ROWS_PER_BLOCK;
    const int nrows = min(ROWS_PER_BLOCK, B - b0);

    // ---- thread 0: compute packed+prescaled weights into smem ----
    if (tid == 0) {
#pragma unroll
        for (int g = 0; g < 2; ++g) {
            const float* wih = g ? dn_wih : up_wih;
            const float* whh = g ? dn_whh : up_whh;
            const float* bih = g ? dn_bih : up_bih;
            const float* bhh = g ? dn_bhh : up_bhh;
            float* W = sw + (g ? W_DN : W_UP);
#pragma unroll
            for (int G = 0; G < 2; ++G) {    // r (rows 0,1), z (rows 2,3)
                float* p = W + G * 10;
                p[0] = 0.5f * wih[4*G + 0]; p[1] = 0.5f * wih[4*G + 2];
                p[2] = 0.5f * wih[4*G + 1]; p[3] = 0.5f * wih[4*G + 3];
                p[4] = 0.5f * whh[4*G + 0]; p[5] = 0.5f * whh[4*G + 2];
                p[6] = 0.5f * whh[4*G + 1]; p[7] = 0.5f * whh[4*G + 3];
                p[8] = 0.5f * (bih[2*G + 0] + bhh[2*G + 0]);
                p[9] = 0.5f * (bih[2*G + 1] + bhh[2*G + 1]);
            }
            // n gate (rows 4,5): gi unscaled, gh scaled by 0.5
            W[20] = wih[8];  W[21] = wih[10];
            W[22] = wih[9];  W[23] = wih[11];
            W[24] = bih[4];  W[25] = bih[5];
            W[26] = 0.5f * whh[8]; W[27] = 0.5f * whh[10];
            W[28] = 0.5f * whh[9]; W[29] = 0.5f * whh[11];
            W[30] = 0.5f * bhh[4]; W[31] = 0.5f * bhh[5];
        }
#pragma unroll
        for (int j = 0; j < 7; ++j) {
            sw[W_OBS + 2*j + 0] = obs_w[j];
            sw[W_OBS + 2*j + 1] = obs_w[7 + j];
        }
        sw[W_OBS + 14] = obs_b[0];
        sw[W_OBS + 15] = obs_b[1];
        sw[W_OUT + 0] = out_w[0];
        sw[W_OUT + 1] = out_w[1];
        sw[W_OUT + 2] = out_b[0];
        sw[W_OUT + 3] = 0.0f;
    }

    // ---- stage input [nrows x 19] coalesced ----
    if (nrows == ROWS_PER_BLOCK) {
        const float4* src = (const float4*)(x + (size_t)b0 * 19);
        float4* dst = (float4*)s;
        constexpr int N4 = ROWS_PER_BLOCK * 19 / 4;   // 1216
#pragma unroll
        for (int i = 0; i < (N4 + TPB - 1) / TPB; ++i) {
            int idx = tid + i * TPB;
            if (idx < N4) dst[idx] = src[idx];
        }
    } else {
        for (int idx = tid; idx < nrows * 19; idx += TPB)
            s[idx] = x[(size_t)b0 * 19 + idx];
    }
    __syncthreads();

    const bool actA = (tid < nrows);
    const bool actB = (tid + TPB < nrows);
    const float* rowA = s + tid * 19;               // 19 odd -> conflict-free
    const float* rowB = s + (tid + TPB) * 19;

    if (actA) {
        float huA0[NSTEP], huA1[NSTEP];
        float huB0[NSTEP], huB1[NSTEP];

        // ---- up GRU: two independent rows share UW regs ----
        u64 UW[16];
        {
            const ulonglong2* p = (const ulonglong2*)(sw + W_UP);
#pragma unroll
            for (int i = 0; i < 8; ++i) { ulonglong2 v = p[i]; UW[2*i] = v.x; UW[2*i+1] = v.y; }
        }
        float hA0 = 0.0f, hA1 = 0.0f, hB0 = 0.0f, hB1 = 0.0f;
#pragma unroll
        for (int t = 0; t < NSTEP; ++t) {
            float aA = rowA[5 + t], bA = rowA[12 + t];
            float aB = actB ? rowB[5 + t] : 0.0f;
            float bB = actB ? rowB[12 + t] : 0.0f;
            gru_cell(pk(aA, aA), pk(bA, bA), hA0, hA1, UW);
            gru_cell(pk(aB, aB), pk(bB, bB), hB0, hB1, UW);
            huA0[t] = hA0; huA1[t] = hA1;
            huB0[t] = hB0; huB1[t] = hB1;
        }

        // ---- obs linear (packed over output lanes), both rows ----
        float gA0, gA1, gB0, gB1;
        {
            u64 OW[8];
            const ulonglong2* p = (const ulonglong2*)(sw + W_OBS);
#pragma unroll
            for (int i = 0; i < 4; ++i) { ulonglong2 v = p[i]; OW[2*i] = v.x; OW[2*i+1] = v.y; }
            u64 cA = OW[7], cB = OW[7];
#pragma unroll
            for (int j = 0; j < 5; ++j) {
                float oA = rowA[j];
                float oB = actB ? rowB[j] : 0.0f;
                cA = fma2_(OW[j], pk(oA, oA), cA);
                cB = fma2_(OW[j], pk(oB, oB), cB);
            }
            cA = fma2_(OW[5], pk(hA0, hA0), cA);
            cA = fma2_(OW[6], pk(hA1, hA1), cA);
            cB = fma2_(OW[5], pk(hB0, hB0), cB);
            cB = fma2_(OW[6], pk(hB1, hB1), cB);
            unpk(cA, gA0, gA1);
            unpk(cB, gB0, gB1);
        }

        // ---- down GRU + per-step output, both rows share DW regs ----
        u64 DW[16];
        {
            const ulonglong2* p = (const ulonglong2*)(sw + W_DN);
#pragma unroll
            for (int i = 0; i < 8; ++i) { ulonglong2 v = p[i]; DW[2*i] = v.x; DW[2*i+1] = v.y; }
        }
        const float4 wo = *(const float4*)(sw + W_OUT);
        float* orowA = so + tid * 7;                // 7 odd -> conflict-free
        float* orowB = so + (tid + TPB) * 7;
#pragma unroll
        for (int t = 0; t < NSTEP; ++t) {
            gru_cell(pk(huA0[t], huA0[t]), pk(huA1[t], huA1[t]), gA0, gA1, DW);
            gru_cell(pk(huB0[t], huB0[t]), pk(huB1[t], huB1[t]), gB0, gB1, DW);
            orowA[t] = fmaf(wo.x, gA0, fmaf(wo.y, gA1, wo.z));
            if (actB) orowB[t] = fmaf(wo.x, gB0, fmaf(wo.y, gB1, wo.z));
        }
    }

    __syncthreads();

    // ---- stage output [nrows x 7] coalesced ----
    if (nrows == ROWS_PER_BLOCK) {
        float4* od = (float4*)(out + (size_t)b0 * 7);
        const float4* ss = (const float4*)so;
        constexpr int N4 = ROWS_PER_BLOCK * 7 / 4;  // 448
#pragma unroll
        for (int i = 0; i < (N4 + TPB - 1) / TPB; ++i) {
            int idx = tid + i * TPB;
            if (idx < N4) od[idx] = ss[idx];
        }
    } else {
        for (int idx = tid; idx < nrows * 7; idx += TPB)
            out[(size_t)b0 * 7 + idx] = so[idx];
    }
}

extern "C" void kernel_launch(void* const* d_in, const int* in_sizes, int n_in,
                              void* d_out, int out_size) {
    const float* x      = (const float*)d_in[0];
    const float* up_wih = (const float*)d_in[1];
    const float* up_whh = (const float*)d_in[2];
    const float* up_bih = (const float*)d_in[3];
    const float* up_bhh = (const float*)d_in[4];
    const float* dn_wih = (const float*)d_in[5];
    const float* dn_whh = (const float*)d_in[6];
    const float* dn_bih = (const float*)d_in[7];
    const float* dn_bhh = (const float*)d_in[8];
    const float* obs_w  = (const float*)d_in[9];
    const float* obs_b  = (const float*)d_in[10];
    const float* out_w  = (const float*)d_in[11];
    const float* out_b  = (const float*)d_in[12];
    float* out = (float*)d_out;

    const int B = in_sizes[0] / 19;
    const int grid = (B + ROWS_PER_BLOCK - 1) / ROWS_PER_BLOCK;
    rec_policy_kernel<<<grid, TPB>>>(x,
                                     up_wih, up_whh, up_bih, up_bhh,
                                     dn_wih, dn_whh, dn_bih, dn_bhh,
                                     obs_w, obs_b, out_w, out_b,
                                     out, B);
}